// round 4
// baseline (speedup 1.0000x reference)
#include <cuda_runtime.h>
#include <cuda_fp16.h>
#include <mma.h>
#include <cstdint>

#define NN 16384
#define EE 524288
#define EPAD (EE + 8 * NN)
#define BB 32
#define DD 64
#define MM 5

using namespace nvcuda;

// ---------------- device scratch (static, allocation-free) ----------------
// fp16 operand buffers, TRANSPOSED layout: buf[(n*32 + b)*64 + d]
__device__ __half g_Xh[(size_t)BB * NN * DD];
__device__ __half g_T1[(size_t)BB * NN * DD];
__device__ __half g_T2[(size_t)BB * NN * DD];
__device__ __half g_T3[(size_t)BB * NN * DD];
__device__ __half g_T4[(size_t)BB * NN * DD];
__device__ __half g_Wh[MM * DD * DD];           // W permuted: [(m*64+k)*64+o]

__device__ float g_degr[NN];
__device__ float g_degc[NN];
__device__ int   g_cnt1[NN], g_cnt2[NN];
__device__ int   g_ptr1[NN + 1], g_ptr2[NN + 1];
__device__ int   g_cur1[NN], g_cur2[NN];
__device__ uint2 g_e1[EPAD], g_e2[EPAD];        // packed (src, val)

// ---------------- init ----------------
__global__ void k_zero() {
    int i = blockIdx.x * blockDim.x + threadIdx.x;
    if (i < NN) {
        g_degr[i] = 0.f; g_degc[i] = 0.f;
        g_cnt1[i] = 0;   g_cnt2[i] = 0;
    }
}

__global__ void k_degree(const int* __restrict__ rows, const int* __restrict__ cols,
                         const float* __restrict__ adj) {
    int e = blockIdx.x * blockDim.x + threadIdx.x;
    if (e >= EE) return;
    int r = rows[e], c = cols[e];
    float a = adj[e];
    atomicAdd(&g_degr[r], a);
    atomicAdd(&g_degc[c], a);
    atomicAdd(&g_cnt1[c], 1);   // S1 scatters to cols
    atomicAdd(&g_cnt2[r], 1);   // S2 scatters to rows
}

// single-block exclusive scan; segments rounded up to multiple of 8, pads zeroed
__device__ void scan16k(const int* __restrict__ cnt, int* __restrict__ ptr,
                        int* __restrict__ cur, uint2* __restrict__ edges, int* sh) {
    int t = threadIdx.x;
    int base = t * 16;
    int loc[16], cr[16], cn[16];
    int s = 0;
#pragma unroll
    for (int j = 0; j < 16; ++j) {
        cn[j] = cnt[base + j];
        cr[j] = (cn[j] + 7) & ~7;       // padded segment length
        loc[j] = s; s += cr[j];
    }
    sh[t] = s;
    __syncthreads();
    for (int off = 1; off < 1024; off <<= 1) {
        int v = (t >= off) ? sh[t - off] : 0;
        __syncthreads();
        sh[t] += v;
        __syncthreads();
    }
    int pre = (t == 0) ? 0 : sh[t - 1];
#pragma unroll
    for (int j = 0; j < 16; ++j) {
        int p = pre + loc[j];
        ptr[base + j] = p;
        cur[base + j] = p;
        for (int q = p + cn[j]; q < p + cr[j]; ++q) edges[q] = make_uint2(0u, 0u);
    }
    if (t == 1023) ptr[NN] = sh[1023];
    __syncthreads();
}

__global__ void k_scan() {
    __shared__ int sh[1024];
    scan16k(g_cnt1, g_ptr1, g_cur1, g_e1, sh);
    scan16k(g_cnt2, g_ptr2, g_cur2, g_e2, sh);
    int t = threadIdx.x;
    for (int i = t; i < NN; i += 1024) {
        float d = g_degr[i]; g_degr[i] = (d > 0.f) ? 1.f / d : 0.f;
        d = g_degc[i];       g_degc[i] = (d > 0.f) ? 1.f / d : 0.f;
    }
}

__global__ void k_fill(const int* __restrict__ rows, const int* __restrict__ cols,
                       const float* __restrict__ adj) {
    int e = blockIdx.x * blockDim.x + threadIdx.x;
    if (e >= EE) return;
    int r = rows[e], c = cols[e];
    float a = adj[e];
    int p = atomicAdd(&g_cur1[c], 1);
    g_e1[p] = make_uint2((unsigned)r, __float_as_uint(a * g_degr[r]));
    int q = atomicAdd(&g_cur2[r], 1);
    g_e2[q] = make_uint2((unsigned)c, __float_as_uint(a * g_degc[c]));
}

// ---------------- converts ----------------
// inputs [b][n][d] fp32 -> g_Xh [(n*32+b)*64+d] fp16 (transpose b<->n)
__global__ void k_cvt_x(const float* __restrict__ X) {
    int i = blockIdx.x * blockDim.x + threadIdx.x;     // half2 index in TARGET
    if (i >= BB * NN * (DD / 2)) return;
    int dh = i & 31;
    int b  = (i >> 5) & 31;
    int n  = i >> 10;
    float2 v = ((const float2*)X)[((size_t)b * NN + n) * 32 + dh];
    ((__half2*)g_Xh)[i] = __floats2half2_rn(v.x, v.y);
}

// permute W [(k*5+m)*64+o] -> g_Wh [(m*64+k)*64+o], fp16
__global__ void k_cvt_w(const float* __restrict__ W) {
    int idx = blockIdx.x * blockDim.x + threadIdx.x;
    if (idx >= MM * DD * DD) return;
    int m = idx / (DD * DD);
    int rem = idx - m * DD * DD;
    int k = rem >> 6, o = rem & 63;
    g_Wh[idx] = __float2half(W[(size_t)(k * MM + m) * DD + o]);
}

// ---------------- SpMM: warp = (dst node, 4 batches), LDG.128 gathers, MLP=8 ----------------
__device__ __forceinline__ void acc8(float2* acc, uint4 g, float v) {
    __half2* h = (__half2*)&g;
#pragma unroll
    for (int k = 0; k < 4; ++k) {
        float2 f = __half22float2(h[k]);
        acc[k].x = fmaf(v, f.x, acc[k].x);
        acc[k].y = fmaf(v, f.y, acc[k].y);
    }
}

template <bool CHEB>
__global__ void __launch_bounds__(256) k_spmm(
    const int* __restrict__ ptr, const uint2* __restrict__ edges,
    const __half* __restrict__ X, const __half* __restrict__ XM,
    __half* __restrict__ T)
{
    int lane = threadIdx.x & 31;
    int n = blockIdx.x * 8 + (threadIdx.x >> 5);
    int quad = blockIdx.y;                               // batches [quad*4, quad*4+4)
    int sub = (quad * 4 + (lane >> 3)) * 8 + (lane & 7); // uint4 index within 4KB node block
    const uint4* __restrict__ Xb = (const uint4*)X;

    int p0 = ptr[n], p1 = ptr[n + 1];                    // segment length multiple of 8
    float2 acc[4] = {{0.f,0.f},{0.f,0.f},{0.f,0.f},{0.f,0.f}};

    for (int base = p0; base < p1; base += 32) {
        int idx = base + lane;
        int s = 0; float v = 0.f;
        if (idx < p1) {
            uint2 e = edges[idx];
            s = (int)e.x; v = __uint_as_float(e.y);
        }
        int cnt = min(32, p1 - base);                    // multiple of 8
        for (int j = 0; j < cnt; j += 8) {
            int ss[8]; float vv[8];
#pragma unroll
            for (int q = 0; q < 8; ++q) {
                ss[q] = __shfl_sync(0xffffffffu, s, j + q);
                vv[q] = __shfl_sync(0xffffffffu, v, j + q);
            }
            uint4 g[8];
#pragma unroll
            for (int q = 0; q < 8; ++q) g[q] = Xb[ss[q] * 256 + sub];
#pragma unroll
            for (int q = 0; q < 8; ++q) acc8(acc, g[q], vv[q]);
        }
    }

    size_t o = (size_t)n * 256 + sub;                    // uint4 units
    if (CHEB) {
        uint4 mg = ((const uint4*)XM)[o];
        __half2* mh = (__half2*)&mg;
#pragma unroll
        for (int k = 0; k < 4; ++k) {
            float2 f = __half22float2(mh[k]);
            acc[k].x = 2.f * acc[k].x - f.x;
            acc[k].y = 2.f * acc[k].y - f.y;
        }
    }
    uint4 r;
    __half2* rh = (__half2*)&r;
#pragma unroll
    for (int k = 0; k < 4; ++k) rh[k] = __floats2half2_rn(acc[k].x, acc[k].y);
    ((uint4*)T)[o] = r;
}

// ---------------- tensor-core projection ----------------
// 512 blocks x 4 warps; each warp sweeps 16 consecutive 16-row tiles.
// A rows are (n*32+b); 16-row tile = one n, b in [0,16) or [16,32).
__global__ void __launch_bounds__(128) k_gemm_tc(
    const __half* __restrict__ Xh, const __half* __restrict__ T1,
    const __half* __restrict__ T2, const __half* __restrict__ T3,
    const __half* __restrict__ T4, const float* __restrict__ bias,
    float* __restrict__ out)
{
    __shared__ __half Wsh[MM * DD * DD];        // 40 KB, loaded ONCE per block
    __shared__ float  Bsh[16 * 64];
    int tid = threadIdx.x;
    int warp = tid >> 5;

    const float4* ws = (const float4*)g_Wh;
    float4* wd = (float4*)Wsh;
#pragma unroll
    for (int i = tid; i < MM * DD * DD / 8; i += 128) wd[i] = ws[i];
#pragma unroll
    for (int i = tid; i < 16 * 64; i += 128) Bsh[i] = bias[i & 63];
    __syncthreads();

    const __half* bufs[5] = {Xh, T1, T2, T3, T4};

    for (int t = 0; t < 16; ++t) {
        int tile = (blockIdx.x * 4 + warp) * 16 + t;
        int r0 = tile * 16;                 // global A row
        int n  = r0 >> 5;
        int b0 = r0 & 31;                   // 0 or 16

        wmma::fragment<wmma::accumulator, 16, 16, 16, float> c[4];
#pragma unroll
        for (int j = 0; j < 4; ++j)
            wmma::load_matrix_sync(c[j], &Bsh[j * 16], 64, wmma::mem_row_major);

#pragma unroll
        for (int m = 0; m < 5; ++m) {
            const __half* A = bufs[m] + (size_t)r0 * DD;
#pragma unroll
            for (int kt = 0; kt < 4; ++kt) {
                wmma::fragment<wmma::matrix_a, 16, 16, 16, __half, wmma::row_major> a;
                wmma::load_matrix_sync(a, A + kt * 16, 64);
#pragma unroll
                for (int j = 0; j < 4; ++j) {
                    wmma::fragment<wmma::matrix_b, 16, 16, 16, __half, wmma::row_major> b;
                    wmma::load_matrix_sync(b, &Wsh[(m * 64 + kt * 16) * 64 + j * 16], 64);
                    wmma::mma_sync(c[j], a, b, c[j]);
                }
            }
        }
        float* ob = out + ((size_t)b0 * NN + n) * DD;
#pragma unroll
        for (int j = 0; j < 4; ++j)
            wmma::store_matrix_sync(ob + j * 16, c[j], NN * DD, wmma::mem_row_major);
    }
}

// ---------------- launch ----------------
extern "C" void kernel_launch(void* const* d_in, const int* in_sizes, int n_in,
                              void* d_out, int out_size)
{
    const float* inputs  = (const float*)d_in[0];   // [B, N, D]
    const float* adj     = (const float*)d_in[1];   // [E]
    const int*   rows    = (const int*)d_in[2];     // [E]
    const int*   cols    = (const int*)d_in[3];     // [E]
    const float* weights = (const float*)d_in[4];   // [D*M, OUT]
    const float* biases  = (const float*)d_in[5];   // [1, OUT]
    float* out = (float*)d_out;                     // [B, N, OUT]
    (void)in_sizes; (void)n_in; (void)out_size;

    void *pP1, *pP2, *pE1, *pE2, *pX, *pT1, *pT2, *pT3, *pT4;
    cudaGetSymbolAddress(&pP1, g_ptr1);
    cudaGetSymbolAddress(&pP2, g_ptr2);
    cudaGetSymbolAddress(&pE1, g_e1);
    cudaGetSymbolAddress(&pE2, g_e2);
    cudaGetSymbolAddress(&pX,  g_Xh);
    cudaGetSymbolAddress(&pT1, g_T1);
    cudaGetSymbolAddress(&pT2, g_T2);
    cudaGetSymbolAddress(&pT3, g_T3);
    cudaGetSymbolAddress(&pT4, g_T4);

    k_zero<<<(NN + 255) / 256, 256>>>();
    k_degree<<<(EE + 255) / 256, 256>>>(rows, cols, adj);
    k_scan<<<1, 1024>>>();
    k_fill<<<(EE + 255) / 256, 256>>>(rows, cols, adj);

    k_cvt_x<<<(BB * NN * (DD / 2) + 255) / 256, 256>>>(inputs);
    k_cvt_w<<<(MM * DD * DD + 255) / 256, 256>>>(weights);

    dim3 sg(NN / 8, 8);
    // T1 = S1 @ X0
    k_spmm<false><<<sg, 256>>>((const int*)pP1, (const uint2*)pE1,
                               (const __half*)pX, nullptr, (__half*)pT1);
    // T2 = 2*S1 @ T1 - X0
    k_spmm<true><<<sg, 256>>>((const int*)pP1, (const uint2*)pE1,
                              (const __half*)pT1, (const __half*)pX, (__half*)pT2);
    // T3 = S2 @ T1
    k_spmm<false><<<sg, 256>>>((const int*)pP2, (const uint2*)pE2,
                               (const __half*)pT1, nullptr, (__half*)pT3);
    // T4 = 2*S2 @ T3 - T1
    k_spmm<true><<<sg, 256>>>((const int*)pP2, (const uint2*)pE2,
                              (const __half*)pT3, (const __half*)pT1, (__half*)pT4);

    k_gemm_tc<<<(BB * NN) / (16 * 64), 128>>>((const __half*)pX, (const __half*)pT1,
                                              (const __half*)pT2, (const __half*)pT3,
                                              (const __half*)pT4, biases, out);
}

// round 5
// speedup vs baseline: 1.0691x; 1.0691x over previous
#include <cuda_runtime.h>
#include <cuda_fp16.h>
#include <mma.h>
#include <cstdint>

#define NN 16384
#define EE 524288
#define EPAD (EE + 4 * NN)
#define BB 32
#define DD 64
#define MM 5

using namespace nvcuda;

// ---------------- device scratch (static, allocation-free) ----------------
// fp16 operand buffers, TRANSPOSED layout: buf[(n*32 + b)*64 + d]
__device__ __half g_Xh[(size_t)BB * NN * DD];
__device__ __half g_T1[(size_t)BB * NN * DD];
__device__ __half g_T2[(size_t)BB * NN * DD];
__device__ __half g_T3[(size_t)BB * NN * DD];
__device__ __half g_T4[(size_t)BB * NN * DD];
__device__ __half g_Wh[MM * DD * DD];           // W permuted: [(m*64+k)*64+o]

__device__ float g_degr[NN];
__device__ float g_degc[NN];
__device__ int   g_cnt1[NN], g_cnt2[NN];
__device__ int   g_ptr1[NN + 1], g_ptr2[NN + 1];
__device__ int   g_cur1[NN], g_cur2[NN];
__device__ int   g_src1[EPAD], g_src2[EPAD];
__device__ float g_val1[EPAD], g_val2[EPAD];

// ---------------- init ----------------
__global__ void k_zero() {
    int i = blockIdx.x * blockDim.x + threadIdx.x;
    if (i < NN) {
        g_degr[i] = 0.f; g_degc[i] = 0.f;
        g_cnt1[i] = 0;   g_cnt2[i] = 0;
    }
}

__global__ void k_degree(const int* __restrict__ rows, const int* __restrict__ cols,
                         const float* __restrict__ adj) {
    int e = blockIdx.x * blockDim.x + threadIdx.x;
    if (e >= EE) return;
    int r = rows[e], c = cols[e];
    float a = adj[e];
    atomicAdd(&g_degr[r], a);
    atomicAdd(&g_degc[c], a);
    atomicAdd(&g_cnt1[c], 1);   // S1 scatters to cols
    atomicAdd(&g_cnt2[r], 1);   // S2 scatters to rows
}

// single-block exclusive scan; segments rounded up to multiple of 4, pads zeroed
__device__ void scan16k(const int* __restrict__ cnt, int* __restrict__ ptr,
                        int* __restrict__ cur, int* __restrict__ src,
                        float* __restrict__ val, int* sh) {
    int t = threadIdx.x;
    int base = t * 16;
    int loc[16], cr[16], cn[16];
    int s = 0;
#pragma unroll
    for (int j = 0; j < 16; ++j) {
        cn[j] = cnt[base + j];
        cr[j] = (cn[j] + 3) & ~3;       // padded segment length
        loc[j] = s; s += cr[j];
    }
    sh[t] = s;
    __syncthreads();
    for (int off = 1; off < 1024; off <<= 1) {
        int v = (t >= off) ? sh[t - off] : 0;
        __syncthreads();
        sh[t] += v;
        __syncthreads();
    }
    int pre = (t == 0) ? 0 : sh[t - 1];
#pragma unroll
    for (int j = 0; j < 16; ++j) {
        int p = pre + loc[j];
        ptr[base + j] = p;
        cur[base + j] = p;
        for (int q = p + cn[j]; q < p + cr[j]; ++q) { src[q] = 0; val[q] = 0.f; }
    }
    if (t == 1023) ptr[NN] = sh[1023];
    __syncthreads();
}

__global__ void k_scan() {
    __shared__ int sh[1024];
    scan16k(g_cnt1, g_ptr1, g_cur1, g_src1, g_val1, sh);
    scan16k(g_cnt2, g_ptr2, g_cur2, g_src2, g_val2, sh);
    int t = threadIdx.x;
    for (int i = t; i < NN; i += 1024) {
        float d = g_degr[i]; g_degr[i] = (d > 0.f) ? 1.f / d : 0.f;
        d = g_degc[i];       g_degc[i] = (d > 0.f) ? 1.f / d : 0.f;
    }
}

__global__ void k_fill(const int* __restrict__ rows, const int* __restrict__ cols,
                       const float* __restrict__ adj) {
    int e = blockIdx.x * blockDim.x + threadIdx.x;
    if (e >= EE) return;
    int r = rows[e], c = cols[e];
    float a = adj[e];
    int p = atomicAdd(&g_cur1[c], 1);
    g_src1[p] = r;
    g_val1[p] = a * g_degr[r];
    int q = atomicAdd(&g_cur2[r], 1);
    g_src2[q] = c;
    g_val2[q] = a * g_degc[c];
}

// ---------------- converts ----------------
// inputs [b][n][d] fp32 -> g_Xh [(n*32+b)*64+d] fp16 (transpose b<->n)
__global__ void k_cvt_x(const float* __restrict__ X) {
    int i = blockIdx.x * blockDim.x + threadIdx.x;     // half2 index in TARGET
    if (i >= BB * NN * (DD / 2)) return;
    int dh = i & 31;
    int b  = (i >> 5) & 31;
    int n  = i >> 10;
    float2 v = ((const float2*)X)[((size_t)b * NN + n) * 32 + dh];
    ((__half2*)g_Xh)[i] = __floats2half2_rn(v.x, v.y);
}

// permute W [(k*5+m)*64+o] -> g_Wh [(m*64+k)*64+o], fp16
__global__ void k_cvt_w(const float* __restrict__ W) {
    int idx = blockIdx.x * blockDim.x + threadIdx.x;
    if (idx >= MM * DD * DD) return;
    int m = idx / (DD * DD);
    int rem = idx - m * DD * DD;
    int k = rem >> 6, o = rem & 63;
    g_Wh[idx] = __float2half(W[(size_t)(k * MM + m) * DD + o]);
}

// ---------------- SpMM (R3-proven): warp = (dst node, 4 batches), LDG.128, MLP=4 ----------------
__device__ __forceinline__ void acc8(float2* acc, uint4 g, float v) {
    __half2* h = (__half2*)&g;
#pragma unroll
    for (int k = 0; k < 4; ++k) {
        float2 f = __half22float2(h[k]);
        acc[k].x = fmaf(v, f.x, acc[k].x);
        acc[k].y = fmaf(v, f.y, acc[k].y);
    }
}

template <bool CHEB>
__global__ void __launch_bounds__(256) k_spmm(
    const int* __restrict__ ptr, const int* __restrict__ srcs,
    const float* __restrict__ vals, const __half* __restrict__ X,
    const __half* __restrict__ XM, __half* __restrict__ T)
{
    int lane = threadIdx.x & 31;
    int n = blockIdx.x * 8 + (threadIdx.x >> 5);
    int quad = blockIdx.y;                               // batches [quad*4, quad*4+4)
    int sub = (quad * 4 + (lane >> 3)) * 8 + (lane & 7); // uint4 index within 4KB node block
    const uint4* __restrict__ Xb = (const uint4*)X;

    int p0 = ptr[n], p1 = ptr[n + 1];                    // segment length multiple of 4
    float2 acc[4] = {{0.f,0.f},{0.f,0.f},{0.f,0.f},{0.f,0.f}};

    for (int base = p0; base < p1; base += 32) {
        int idx = base + lane;
        int s = 0; float v = 0.f;
        if (idx < p1) { s = srcs[idx]; v = vals[idx]; }
        int cnt = min(32, p1 - base);                    // multiple of 4
        for (int j = 0; j < cnt; j += 4) {
            int s0 = __shfl_sync(0xffffffffu, s, j);
            int s1 = __shfl_sync(0xffffffffu, s, j + 1);
            int s2 = __shfl_sync(0xffffffffu, s, j + 2);
            int s3 = __shfl_sync(0xffffffffu, s, j + 3);
            float v0 = __shfl_sync(0xffffffffu, v, j);
            float v1 = __shfl_sync(0xffffffffu, v, j + 1);
            float v2 = __shfl_sync(0xffffffffu, v, j + 2);
            float v3 = __shfl_sync(0xffffffffu, v, j + 3);
            uint4 g0 = Xb[s0 * 256 + sub];
            uint4 g1 = Xb[s1 * 256 + sub];
            uint4 g2 = Xb[s2 * 256 + sub];
            uint4 g3 = Xb[s3 * 256 + sub];
            acc8(acc, g0, v0);
            acc8(acc, g1, v1);
            acc8(acc, g2, v2);
            acc8(acc, g3, v3);
        }
    }

    size_t o = (size_t)n * 256 + sub;                    // uint4 units
    if (CHEB) {
        uint4 mg = ((const uint4*)XM)[o];
        __half2* mh = (__half2*)&mg;
#pragma unroll
        for (int k = 0; k < 4; ++k) {
            float2 f = __half22float2(mh[k]);
            acc[k].x = 2.f * acc[k].x - f.x;
            acc[k].y = 2.f * acc[k].y - f.y;
        }
    }
    uint4 r;
    __half2* rh = (__half2*)&r;
#pragma unroll
    for (int k = 0; k < 4; ++k) rh[k] = __floats2half2_rn(acc[k].x, acc[k].y);
    ((uint4*)T)[o] = r;
}

// ---------------- tensor-core projection ----------------
// 1024 blocks x 8 warps; each warp sweeps 4 consecutive 16-row tiles.
// A rows are (n*32+b); 16-row tile = one n, b in [0,16) or [16,32).
__global__ void __launch_bounds__(256) k_gemm_tc(
    const __half* __restrict__ Xh, const __half* __restrict__ T1,
    const __half* __restrict__ T2, const __half* __restrict__ T3,
    const __half* __restrict__ T4, const float* __restrict__ bias,
    float* __restrict__ out)
{
    __shared__ __half Wsh[MM * DD * DD];        // 40 KB, loaded ONCE per block
    __shared__ float  Bsh[16 * 64];
    int tid = threadIdx.x;
    int warp = tid >> 5;

    const float4* ws = (const float4*)g_Wh;
    float4* wd = (float4*)Wsh;
#pragma unroll
    for (int i = tid; i < MM * DD * DD / 8; i += 256) wd[i] = ws[i];
#pragma unroll
    for (int i = tid; i < 16 * 64; i += 256) Bsh[i] = bias[i & 63];
    __syncthreads();

    const __half* bufs[5] = {Xh, T1, T2, T3, T4};

#pragma unroll
    for (int t = 0; t < 4; ++t) {
        int tile = (blockIdx.x * 8 + warp) * 4 + t;
        int r0 = tile * 16;                 // global A row
        int n  = r0 >> 5;
        int b0 = r0 & 31;                   // 0 or 16

        wmma::fragment<wmma::accumulator, 16, 16, 16, float> c[4];
#pragma unroll
        for (int j = 0; j < 4; ++j)
            wmma::load_matrix_sync(c[j], &Bsh[j * 16], 64, wmma::mem_row_major);

#pragma unroll
        for (int m = 0; m < 5; ++m) {
            const __half* A = bufs[m] + (size_t)r0 * DD;
#pragma unroll
            for (int kt = 0; kt < 4; ++kt) {
                wmma::fragment<wmma::matrix_a, 16, 16, 16, __half, wmma::row_major> a;
                wmma::load_matrix_sync(a, A + kt * 16, 64);
#pragma unroll
                for (int j = 0; j < 4; ++j) {
                    wmma::fragment<wmma::matrix_b, 16, 16, 16, __half, wmma::row_major> b;
                    wmma::load_matrix_sync(b, &Wsh[(m * 64 + kt * 16) * 64 + j * 16], 64);
                    wmma::mma_sync(c[j], a, b, c[j]);
                }
            }
        }
        float* ob = out + ((size_t)b0 * NN + n) * DD;
#pragma unroll
        for (int j = 0; j < 4; ++j)
            wmma::store_matrix_sync(ob + j * 16, c[j], NN * DD, wmma::mem_row_major);
    }
}

// ---------------- launch ----------------
extern "C" void kernel_launch(void* const* d_in, const int* in_sizes, int n_in,
                              void* d_out, int out_size)
{
    const float* inputs  = (const float*)d_in[0];   // [B, N, D]
    const float* adj     = (const float*)d_in[1];   // [E]
    const int*   rows    = (const int*)d_in[2];     // [E]
    const int*   cols    = (const int*)d_in[3];     // [E]
    const float* weights = (const float*)d_in[4];   // [D*M, OUT]
    const float* biases  = (const float*)d_in[5];   // [1, OUT]
    float* out = (float*)d_out;                     // [B, N, OUT]
    (void)in_sizes; (void)n_in; (void)out_size;

    void *pP1, *pP2, *pS1, *pS2, *pV1, *pV2, *pX, *pT1, *pT2, *pT3, *pT4;
    cudaGetSymbolAddress(&pP1, g_ptr1);
    cudaGetSymbolAddress(&pP2, g_ptr2);
    cudaGetSymbolAddress(&pS1, g_src1);
    cudaGetSymbolAddress(&pS2, g_src2);
    cudaGetSymbolAddress(&pV1, g_val1);
    cudaGetSymbolAddress(&pV2, g_val2);
    cudaGetSymbolAddress(&pX,  g_Xh);
    cudaGetSymbolAddress(&pT1, g_T1);
    cudaGetSymbolAddress(&pT2, g_T2);
    cudaGetSymbolAddress(&pT3, g_T3);
    cudaGetSymbolAddress(&pT4, g_T4);

    k_zero<<<(NN + 255) / 256, 256>>>();
    k_degree<<<(EE + 255) / 256, 256>>>(rows, cols, adj);
    k_scan<<<1, 1024>>>();
    k_fill<<<(EE + 255) / 256, 256>>>(rows, cols, adj);

    k_cvt_x<<<(BB * NN * (DD / 2) + 255) / 256, 256>>>(inputs);
    k_cvt_w<<<(MM * DD * DD + 255) / 256, 256>>>(weights);

    dim3 sg(NN / 8, 8);
    // T1 = S1 @ X0
    k_spmm<false><<<sg, 256>>>((const int*)pP1, (const int*)pS1, (const float*)pV1,
                               (const __half*)pX, nullptr, (__half*)pT1);
    // T2 = 2*S1 @ T1 - X0
    k_spmm<true><<<sg, 256>>>((const int*)pP1, (const int*)pS1, (const float*)pV1,
                              (const __half*)pT1, (const __half*)pX, (__half*)pT2);
    // T3 = S2 @ T1
    k_spmm<false><<<sg, 256>>>((const int*)pP2, (const int*)pS2, (const float*)pV2,
                               (const __half*)pT1, nullptr, (__half*)pT3);
    // T4 = 2*S2 @ T3 - T1
    k_spmm<true><<<sg, 256>>>((const int*)pP2, (const int*)pS2, (const float*)pV2,
                              (const __half*)pT3, (const __half*)pT1, (__half*)pT4);

    k_gemm_tc<<<(BB * NN) / (4 * 8 * 16), 256>>>((const __half*)pX, (const __half*)pT1,
                                                 (const __half*)pT2, (const __half*)pT3,
                                                 (const __half*)pT4, biases, out);
}